// round 15
// baseline (speedup 1.0000x reference)
#include <cuda_runtime.h>

// z_hat [B,T,D] f32, P [B,T] f32, lengths [B] i32 -> out [B,T,D] f32
#define BB 4
#define TT 4096
#define DD 512
#define CC 256          // chunks along T (best-known config)
#define LL 16           // chunk length
#define D4 (DD/4)       // float4 lanes per row (128)

// Scratch (__device__ globals; allocation-free rule)
__device__ float g_Bsum[BB * CC * DD];
__device__ float g_A[BB * CC];
__device__ float g_Zinit[BB * CC * DD];

// ---------------------------------------------------------------------------
// K1: grid (BB, CC, 2).
//  z==0: per-chunk weighted reduction (skip masked chunks).
//  z==1: zero-fill the OUTPUT rows of masked chunks (skip active chunks).
// The fill blocks are independent and execute inside the summary blocks'
// latency bubbles, taking 16MB of stores off k3's critical path.
// ---------------------------------------------------------------------------
__global__ void __launch_bounds__(128) k1_chunk_summary(
    const float* __restrict__ z, const float* __restrict__ P,
    const int* __restrict__ lengths, float* __restrict__ out)
{
    const int b = blockIdx.x;     // fastest -> masked/active mixed across SMs
    const int c = blockIdx.y;
    const int lane = threadIdx.x; // float4 lane over D
    const int len = lengths[b];
    const int t0 = c * LL;

    if (blockIdx.z == 1) {
        // fill slice: handle only fully-masked chunks
        if (t0 < len) return;
        float4* __restrict__ op = (float4*)(out + ((size_t)b * TT + t0) * DD);
        float4 zero = make_float4(0.f, 0.f, 0.f, 0.f);
#pragma unroll
        for (int k = 0; k < LL; ++k) op[(size_t)k * D4 + lane] = zero;
        return;
    }

    if (t0 >= len) return;        // masked chunk: state never consumed

    __shared__ float sw[LL];
    __shared__ float sq[LL], sp[LL];

    if (lane < LL) {
        float p = P[b * TT + t0 + lane];
        p = fminf(fmaxf(p, 0.0f), 1.0f - 1e-6f);
        sq[lane] = 1.0f - p;
        sp[lane] = fmaxf(p, 1e-6f);
    }
    __syncthreads();
    if (lane == 0) {
        float r = 1.0f;
#pragma unroll
        for (int k = LL - 1; k >= 0; --k) { sw[k] = sp[k] * r; r *= sq[k]; }
        g_A[b * CC + c] = r;
    }
    __syncthreads();

    const float4* __restrict__ zp =
        (const float4*)(z + ((size_t)b * TT + t0) * DD);

    float4 acc = make_float4(0.f, 0.f, 0.f, 0.f);
#pragma unroll
    for (int kb = 0; kb < LL; kb += 8) {
        float4 x0 = zp[(size_t)(kb + 0) * D4 + lane];
        float4 x1 = zp[(size_t)(kb + 1) * D4 + lane];
        float4 x2 = zp[(size_t)(kb + 2) * D4 + lane];
        float4 x3 = zp[(size_t)(kb + 3) * D4 + lane];
        float4 x4 = zp[(size_t)(kb + 4) * D4 + lane];
        float4 x5 = zp[(size_t)(kb + 5) * D4 + lane];
        float4 x6 = zp[(size_t)(kb + 6) * D4 + lane];
        float4 x7 = zp[(size_t)(kb + 7) * D4 + lane];
        float w0 = sw[kb + 0], w1 = sw[kb + 1], w2 = sw[kb + 2], w3 = sw[kb + 3];
        float w4 = sw[kb + 4], w5 = sw[kb + 5], w6 = sw[kb + 6], w7 = sw[kb + 7];
        acc.x = fmaf(w0, x0.x, acc.x); acc.y = fmaf(w0, x0.y, acc.y);
        acc.z = fmaf(w0, x0.z, acc.z); acc.w = fmaf(w0, x0.w, acc.w);
        acc.x = fmaf(w1, x1.x, acc.x); acc.y = fmaf(w1, x1.y, acc.y);
        acc.z = fmaf(w1, x1.z, acc.z); acc.w = fmaf(w1, x1.w, acc.w);
        acc.x = fmaf(w2, x2.x, acc.x); acc.y = fmaf(w2, x2.y, acc.y);
        acc.z = fmaf(w2, x2.z, acc.z); acc.w = fmaf(w2, x2.w, acc.w);
        acc.x = fmaf(w3, x3.x, acc.x); acc.y = fmaf(w3, x3.y, acc.y);
        acc.z = fmaf(w3, x3.z, acc.z); acc.w = fmaf(w3, x3.w, acc.w);
        acc.x = fmaf(w4, x4.x, acc.x); acc.y = fmaf(w4, x4.y, acc.y);
        acc.z = fmaf(w4, x4.z, acc.z); acc.w = fmaf(w4, x4.w, acc.w);
        acc.x = fmaf(w5, x5.x, acc.x); acc.y = fmaf(w5, x5.y, acc.y);
        acc.z = fmaf(w5, x5.z, acc.z); acc.w = fmaf(w5, x5.w, acc.w);
        acc.x = fmaf(w6, x6.x, acc.x); acc.y = fmaf(w6, x6.y, acc.y);
        acc.z = fmaf(w6, x6.z, acc.z); acc.w = fmaf(w6, x6.w, acc.w);
        acc.x = fmaf(w7, x7.x, acc.x); acc.y = fmaf(w7, x7.y, acc.y);
        acc.z = fmaf(w7, x7.z, acc.z); acc.w = fmaf(w7, x7.w, acc.w);
    }
    ((float4*)g_Bsum)[(size_t)(b * CC + c) * D4 + lane] = acc;
}

// ---------------------------------------------------------------------------
// K2: parallel cross-chunk scan (Hillis-Steele over affine maps), verbatim
// from R5. Block = (b, d4-lane). Thread c owns chunk c's map.
// ---------------------------------------------------------------------------
__global__ void __launch_bounds__(CC) k2_scan()
{
    const int b = blockIdx.x;
    const int g = blockIdx.y;     // d4 lane 0..127
    const int c = threadIdx.x;    // chunk id 0..CC-1

    __shared__ float sA[CC];
    __shared__ float4 sB[CC];

    float a = g_A[b * CC + c];
    float4 v = ((const float4*)g_Bsum)[(size_t)(b * CC + c) * D4 + g];
    sA[c] = a; sB[c] = v;
    __syncthreads();

#pragma unroll
    for (int s = 1; s < CC; s <<= 1) {
        float pa = 1.0f;
        float4 pb = make_float4(0.f, 0.f, 0.f, 0.f);
        if (c >= s) { pa = sA[c - s]; pb = sB[c - s]; }
        __syncthreads();
        if (c >= s) {
            v.x = fmaf(a, pb.x, v.x);
            v.y = fmaf(a, pb.y, v.y);
            v.z = fmaf(a, pb.z, v.z);
            v.w = fmaf(a, pb.w, v.w);
            a *= pa;
            sA[c] = a; sB[c] = v;
        }
        __syncthreads();
    }

    float4 zo = (c == 0) ? make_float4(0.f, 0.f, 0.f, 0.f) : sB[c - 1];
    ((float4*)g_Zinit)[(size_t)(b * CC + c) * D4 + g] = zo;
}

// ---------------------------------------------------------------------------
// K3: per-chunk local scan seeded with Zinit (R5 verbatim), except masked
// chunks now exit immediately — their zeros were written by K1's fill slice.
// ---------------------------------------------------------------------------
__global__ void __launch_bounds__(128) k3_scan_out(
    const float* __restrict__ z, const float* __restrict__ P,
    const int* __restrict__ lengths, float* __restrict__ out)
{
    const int b = blockIdx.x;
    const int c = blockIdx.y;
    const int lane = threadIdx.x;
    const int len = lengths[b];
    const int t0 = c * LL;
    if (t0 >= len) return;        // zero-filled by K1's fill slice

    __shared__ float sp[LL], sq[LL];

    // carry load issued early, latency hidden behind P/smem setup
    float4 zv = ((const float4*)g_Zinit)[(size_t)(b * CC + c) * D4 + lane];

    if (lane < LL) {
        float p = P[b * TT + t0 + lane];
        p = fminf(fmaxf(p, 0.0f), 1.0f - 1e-6f);
        sq[lane] = 1.0f - p;
        sp[lane] = fmaxf(p, 1e-6f);
    }
    __syncthreads();

    const float4* __restrict__ zp =
        (const float4*)(z + ((size_t)b * TT + t0) * DD);
    float4* __restrict__ op = (float4*)(out + ((size_t)b * TT + t0) * DD);

#pragma unroll
    for (int kb = 0; kb < LL; kb += 8) {
        float4 x0 = zp[(size_t)(kb + 0) * D4 + lane];
        float4 x1 = zp[(size_t)(kb + 1) * D4 + lane];
        float4 x2 = zp[(size_t)(kb + 2) * D4 + lane];
        float4 x3 = zp[(size_t)(kb + 3) * D4 + lane];
        float4 x4 = zp[(size_t)(kb + 4) * D4 + lane];
        float4 x5 = zp[(size_t)(kb + 5) * D4 + lane];
        float4 x6 = zp[(size_t)(kb + 6) * D4 + lane];
        float4 x7 = zp[(size_t)(kb + 7) * D4 + lane];
#pragma unroll
        for (int j = 0; j < 8; ++j) {
            const int kk = kb + j;
            float4 x = (j == 0) ? x0 : (j == 1) ? x1 : (j == 2) ? x2 : (j == 3) ? x3
                     : (j == 4) ? x4 : (j == 5) ? x5 : (j == 6) ? x6 : x7;
            float q = sq[kk], p = sp[kk];
            zv.x = fmaf(q, zv.x, p * x.x);
            zv.y = fmaf(q, zv.y, p * x.y);
            zv.z = fmaf(q, zv.z, p * x.z);
            zv.w = fmaf(q, zv.w, p * x.w);
            float m = (t0 + kk < len) ? 1.0f : 0.0f;
            op[(size_t)kk * D4 + lane] =
                make_float4(zv.x * m, zv.y * m, zv.z * m, zv.w * m);
        }
    }
}

extern "C" void kernel_launch(void* const* d_in, const int* in_sizes, int n_in,
                              void* d_out, int out_size)
{
    const float* z = (const float*)d_in[0];
    const float* P = (const float*)d_in[1];
    const int* lengths = (const int*)d_in[2];
    float* out = (float*)d_out;

    dim3 gridA(BB, CC, 2);     // z=0 summaries, z=1 masked-output zero-fill
    k1_chunk_summary<<<gridA, 128>>>(z, P, lengths, out);
    dim3 gridS(BB, D4);
    k2_scan<<<gridS, CC>>>();
    dim3 gridC(BB, CC);
    k3_scan_out<<<gridC, 128>>>(z, P, lengths, out);
}

// round 16
// speedup vs baseline: 1.0804x; 1.0804x over previous
#include <cuda_runtime.h>

// z_hat [B,T,D] f32, P [B,T] f32, lengths [B] i32 -> out [B,T,D] f32
#define BB 4
#define TT 4096
#define DD 512
#define CC 256          // chunks along T (best-known config)
#define LL 16           // chunk length
#define D4 (DD/4)       // float4 lanes per row (128)

// Scratch (__device__ globals; allocation-free rule). idx f = b*CC + c.
__device__ float g_Bsum[BB * CC * DD];
__device__ float g_A[BB * CC];
__device__ float g_Zinit[BB * CC * DD];

// ---------------------------------------------------------------------------
// K1: per-chunk weighted reduction, R13 phase-A style: per-thread register
// weights from broadcast P loads, no smem, no __syncthreads. Measured faster
// than the smem-prologue variant.
// ---------------------------------------------------------------------------
__global__ void __launch_bounds__(128, 8) k1_chunk_summary(
    const float* __restrict__ z, const float* __restrict__ P,
    const int* __restrict__ lengths)
{
    const int b = blockIdx.x;     // fastest -> masked/active mixed across SMs
    const int c = blockIdx.y;
    const int lane = threadIdx.x; // float4 lane over D
    const int len = lengths[b];
    const int t0 = c * LL;
    if (t0 >= len) return;        // masked chunk: state never consumed

    float pcl[LL];
#pragma unroll
    for (int k = 0; k < LL; ++k) {
        float p = __ldg(&P[b * TT + t0 + k]);     // warp-uniform broadcast
        pcl[k] = fminf(fmaxf(p, 0.0f), 1.0f - 1e-6f);
    }
    float w[LL];
    float r = 1.0f;
#pragma unroll
    for (int k = LL - 1; k >= 0; --k) {
        w[k] = fmaxf(pcl[k], 1e-6f) * r;          // w[k]=pe[k]*prod_{m>k}q[m]
        r *= (1.0f - pcl[k]);
    }

    const float4* __restrict__ zp =
        (const float4*)(z + ((size_t)b * TT + t0) * DD);
    float4 a0 = make_float4(0.f, 0.f, 0.f, 0.f);
    float4 a1 = make_float4(0.f, 0.f, 0.f, 0.f);
#pragma unroll
    for (int kb = 0; kb < LL; kb += 8) {
        float4 x0 = zp[(size_t)(kb + 0) * D4 + lane];
        float4 x1 = zp[(size_t)(kb + 1) * D4 + lane];
        float4 x2 = zp[(size_t)(kb + 2) * D4 + lane];
        float4 x3 = zp[(size_t)(kb + 3) * D4 + lane];
        float4 x4 = zp[(size_t)(kb + 4) * D4 + lane];
        float4 x5 = zp[(size_t)(kb + 5) * D4 + lane];
        float4 x6 = zp[(size_t)(kb + 6) * D4 + lane];
        float4 x7 = zp[(size_t)(kb + 7) * D4 + lane];
        asm volatile("" ::: "memory");
        a0.x = fmaf(w[kb+0], x0.x, a0.x); a0.y = fmaf(w[kb+0], x0.y, a0.y);
        a0.z = fmaf(w[kb+0], x0.z, a0.z); a0.w = fmaf(w[kb+0], x0.w, a0.w);
        a1.x = fmaf(w[kb+1], x1.x, a1.x); a1.y = fmaf(w[kb+1], x1.y, a1.y);
        a1.z = fmaf(w[kb+1], x1.z, a1.z); a1.w = fmaf(w[kb+1], x1.w, a1.w);
        a0.x = fmaf(w[kb+2], x2.x, a0.x); a0.y = fmaf(w[kb+2], x2.y, a0.y);
        a0.z = fmaf(w[kb+2], x2.z, a0.z); a0.w = fmaf(w[kb+2], x2.w, a0.w);
        a1.x = fmaf(w[kb+3], x3.x, a1.x); a1.y = fmaf(w[kb+3], x3.y, a1.y);
        a1.z = fmaf(w[kb+3], x3.z, a1.z); a1.w = fmaf(w[kb+3], x3.w, a1.w);
        a0.x = fmaf(w[kb+4], x4.x, a0.x); a0.y = fmaf(w[kb+4], x4.y, a0.y);
        a0.z = fmaf(w[kb+4], x4.z, a0.z); a0.w = fmaf(w[kb+4], x4.w, a0.w);
        a1.x = fmaf(w[kb+5], x5.x, a1.x); a1.y = fmaf(w[kb+5], x5.y, a1.y);
        a1.z = fmaf(w[kb+5], x5.z, a1.z); a1.w = fmaf(w[kb+5], x5.w, a1.w);
        a0.x = fmaf(w[kb+6], x6.x, a0.x); a0.y = fmaf(w[kb+6], x6.y, a0.y);
        a0.z = fmaf(w[kb+6], x6.z, a0.z); a0.w = fmaf(w[kb+6], x6.w, a0.w);
        a1.x = fmaf(w[kb+7], x7.x, a1.x); a1.y = fmaf(w[kb+7], x7.y, a1.y);
        a1.z = fmaf(w[kb+7], x7.z, a1.z); a1.w = fmaf(w[kb+7], x7.w, a1.w);
    }
    const int f = b * CC + c;
    ((float4*)g_Bsum)[(size_t)f * D4 + lane] =
        make_float4(a0.x + a1.x, a0.y + a1.y, a0.z + a1.z, a0.w + a1.w);
    if (lane == 0) g_A[f] = r;
}

// ---------------------------------------------------------------------------
// K2: pair-combined Hillis-Steele over the CC=256 affine maps (R13 phase-B
// standalone). Block = (b, d4-lane g), 128 threads; thread i owns chunk pair
// (2i, 2i+1). Composition (A2,B2)∘(A1,B1) = (A2*A1, A2*B1+B2). Garbage in
// masked chunks only flows toward higher c -> never consumed.
// ---------------------------------------------------------------------------
__global__ void __launch_bounds__(128) k2_scan()
{
    const int b = blockIdx.x;
    const int g = blockIdx.y;     // d4 lane 0..127
    const int i = threadIdx.x;    // pair id 0..127

    const int f0 = b * CC + 2 * i;
    const int f1 = f0 + 1;

    float a0 = g_A[f0];
    float a1 = g_A[f1];
    float4 v0 = ((const float4*)g_Bsum)[(size_t)f0 * D4 + g];
    float4 v1 = ((const float4*)g_Bsum)[(size_t)f1 * D4 + g];

    float  ac = a1 * a0;
    float4 bc = make_float4(fmaf(a1, v0.x, v1.x), fmaf(a1, v0.y, v1.y),
                            fmaf(a1, v0.z, v1.z), fmaf(a1, v0.w, v1.w));

    __shared__ float sA[128];
    __shared__ float4 sB[128];
    sA[i] = ac; sB[i] = bc;
    __syncthreads();
#pragma unroll
    for (int s = 1; s < 128; s <<= 1) {
        float pa = 1.0f;
        float4 pb = make_float4(0.f, 0.f, 0.f, 0.f);
        if (i >= s) { pa = sA[i - s]; pb = sB[i - s]; }
        __syncthreads();
        if (i >= s) {
            bc.x = fmaf(ac, pb.x, bc.x);
            bc.y = fmaf(ac, pb.y, bc.y);
            bc.z = fmaf(ac, pb.z, bc.z);
            bc.w = fmaf(ac, pb.w, bc.w);
            ac *= pa;
            sA[i] = ac; sB[i] = bc;
        }
        __syncthreads();
    }
    float4 Eb = (i == 0) ? make_float4(0.f, 0.f, 0.f, 0.f) : sB[i - 1];
    float4* __restrict__ zi = (float4*)g_Zinit;
    zi[(size_t)f0 * D4 + g] = Eb;
    zi[(size_t)f1 * D4 + g] =
        make_float4(fmaf(a0, Eb.x, v0.x), fmaf(a0, Eb.y, v0.y),
                    fmaf(a0, Eb.z, v0.z), fmaf(a0, Eb.w, v0.w));
}

// ---------------------------------------------------------------------------
// K3: VERBATIM from the 17.15us R5 run. Per-chunk local scan seeded with
// Zinit; mask; write out. Fully-masked chunks write zeros, no loads.
// ---------------------------------------------------------------------------
__global__ void __launch_bounds__(128) k3_scan_out(
    const float* __restrict__ z, const float* __restrict__ P,
    const int* __restrict__ lengths, float* __restrict__ out)
{
    const int b = blockIdx.x;
    const int c = blockIdx.y;
    const int lane = threadIdx.x;
    const int len = lengths[b];
    const int t0 = c * LL;

    float4* __restrict__ op = (float4*)(out + ((size_t)b * TT + t0) * DD);

    if (t0 >= len) {
        float4 zero = make_float4(0.f, 0.f, 0.f, 0.f);
#pragma unroll
        for (int k = 0; k < LL; ++k) op[(size_t)k * D4 + lane] = zero;
        return;
    }

    __shared__ float sp[LL], sq[LL];

    // carry load issued early, latency hidden behind P/smem setup
    float4 zv = ((const float4*)g_Zinit)[(size_t)(b * CC + c) * D4 + lane];

    if (lane < LL) {
        float p = P[b * TT + t0 + lane];
        p = fminf(fmaxf(p, 0.0f), 1.0f - 1e-6f);
        sq[lane] = 1.0f - p;
        sp[lane] = fmaxf(p, 1e-6f);
    }
    __syncthreads();

    const float4* __restrict__ zp =
        (const float4*)(z + ((size_t)b * TT + t0) * DD);

#pragma unroll
    for (int kb = 0; kb < LL; kb += 8) {
        float4 x0 = zp[(size_t)(kb + 0) * D4 + lane];
        float4 x1 = zp[(size_t)(kb + 1) * D4 + lane];
        float4 x2 = zp[(size_t)(kb + 2) * D4 + lane];
        float4 x3 = zp[(size_t)(kb + 3) * D4 + lane];
        float4 x4 = zp[(size_t)(kb + 4) * D4 + lane];
        float4 x5 = zp[(size_t)(kb + 5) * D4 + lane];
        float4 x6 = zp[(size_t)(kb + 6) * D4 + lane];
        float4 x7 = zp[(size_t)(kb + 7) * D4 + lane];
#pragma unroll
        for (int j = 0; j < 8; ++j) {
            const int kk = kb + j;
            float4 x = (j == 0) ? x0 : (j == 1) ? x1 : (j == 2) ? x2 : (j == 3) ? x3
                     : (j == 4) ? x4 : (j == 5) ? x5 : (j == 6) ? x6 : x7;
            float q = sq[kk], p = sp[kk];
            zv.x = fmaf(q, zv.x, p * x.x);
            zv.y = fmaf(q, zv.y, p * x.y);
            zv.z = fmaf(q, zv.z, p * x.z);
            zv.w = fmaf(q, zv.w, p * x.w);
            float m = (t0 + kk < len) ? 1.0f : 0.0f;
            op[(size_t)kk * D4 + lane] =
                make_float4(zv.x * m, zv.y * m, zv.z * m, zv.w * m);
        }
    }
}

extern "C" void kernel_launch(void* const* d_in, const int* in_sizes, int n_in,
                              void* d_out, int out_size)
{
    const float* z = (const float*)d_in[0];
    const float* P = (const float*)d_in[1];
    const int* lengths = (const int*)d_in[2];
    float* out = (float*)d_out;

    dim3 gridA(BB, CC);        // b fastest -> masked/active mixed across SMs
    k1_chunk_summary<<<gridA, 128>>>(z, P, lengths);
    dim3 gridS(BB, D4);
    k2_scan<<<gridS, 128>>>();
    k3_scan_out<<<gridA, 128>>>(z, P, lengths, out);
}